// round 4
// baseline (speedup 1.0000x reference)
#include <cuda_runtime.h>
#include <cstdint>

#define SEQ   4096
#define HID   1280
#define NH    16
#define HD    80
#define HID3  3840
#define IMG_BLK 1024
#define ATT_SCALE 0.11180339887498949f  /* 80^-0.5 */

/* ------------ scratch (device globals: allocation-free rule) ------------- */
__device__ float    g_qkv[(size_t)SEQ * HID3];
__device__ float    g_att[(size_t)SEQ * HID];
__device__ uint32_t g_q[(size_t)NH * SEQ * HD];
__device__ uint32_t g_k[(size_t)NH * SEQ * HD];
__device__ uint32_t g_v[(size_t)NH * SEQ * HD];

/* ----------------------------- helpers ---------------------------------- */
__device__ __forceinline__ void cp_async16(void* smem, const void* gmem) {
    uint32_t s = (uint32_t)__cvta_generic_to_shared(smem);
    asm volatile("cp.async.ca.shared.global [%0], [%1], 16;\n" :: "r"(s), "l"(gmem));
}
__device__ __forceinline__ void cp_commit() {
    asm volatile("cp.async.commit_group;\n" ::: "memory");
}
__device__ __forceinline__ void cp_wait0() {
    asm volatile("cp.async.wait_group 0;\n" ::: "memory");
}
__device__ __forceinline__ void cp_wait1() {
    asm volatile("cp.async.wait_group 1;\n" ::: "memory");
}

/* m16n8k8 tf32 mma, D += A*B (fp32 accum). Operands pre-rounded +0x1000. */
__device__ __forceinline__ void mma_tf32(float* d, const uint32_t* a, const uint32_t* b) {
    asm volatile(
        "mma.sync.aligned.m16n8k8.row.col.f32.tf32.tf32.f32 "
        "{%0,%1,%2,%3}, {%4,%5,%6,%7}, {%8,%9}, {%0,%1,%2,%3};\n"
        : "+f"(d[0]), "+f"(d[1]), "+f"(d[2]), "+f"(d[3])
        : "r"(a[0]), "r"(a[1]), "r"(a[2]), "r"(a[3]),
          "r"(b[0]), "r"(b[1]));
}

/* ======================== GEMM: C = A * B^T + bias =======================
   A [M,K] fp32 row-major, B [N,K] fp32 row-major (weights), C [M,N].
   Block tile 128x128, BK=32, 8 warps (warp tile 64x32), tf32 mma,
   cp.async 2-stage dynamic smem. M,N mult of 128; K mult of 32. */
#define GBM 128
#define GBN 128
#define GBK 32
#define GPAD 36   /* 32 + 4: bank-conflict-free frag loads */
#define GEMM_SMEM (4 * 128 * GPAD * 4)   /* 73728 B */

__global__ __launch_bounds__(256, 2)
void gemm_bias_kernel(const float* __restrict__ A, const float* __restrict__ B,
                      const float* __restrict__ bias, float* __restrict__ C,
                      int M, int N, int K)
{
    extern __shared__ float gsm[];
    float* Asm[2] = { gsm,                gsm + 128 * GPAD };
    float* Bsm[2] = { gsm + 2 * 128 * GPAD, gsm + 3 * 128 * GPAD };

    const int tid  = threadIdx.x;
    const int lane = tid & 31;
    const int warp = tid >> 5;
    const int wm   = (warp & 1) * 64;
    const int wn   = (warp >> 1) * 32;
    const int m0   = blockIdx.y * GBM;
    const int n0   = blockIdx.x * GBN;
    const int KT   = K / GBK;

    float acc[4][4][4];
#pragma unroll
    for (int mt = 0; mt < 4; mt++)
#pragma unroll
        for (int nt = 0; nt < 4; nt++)
#pragma unroll
            for (int r = 0; r < 4; r++) acc[mt][nt][r] = 0.f;

    /* loader: 128 rows x 128B per operand = 1024 chunks; 4 per thread each */
    auto issue = [&](int kt, int buf) {
        int k0 = kt * GBK;
#pragma unroll
        for (int i = 0; i < 4; i++) {
            int idx = tid + (i << 8);
            int row = idx >> 3;
            int fc  = (idx & 7) << 2;
            cp_async16(&Asm[buf][row * GPAD + fc], &A[(size_t)(m0 + row) * K + k0 + fc]);
            cp_async16(&Bsm[buf][row * GPAD + fc], &B[(size_t)(n0 + row) * K + k0 + fc]);
        }
        cp_commit();
    };

    issue(0, 0);

#pragma unroll 1
    for (int kt = 0; kt < KT; kt++) {
        int buf = kt & 1;
        if (kt + 1 < KT) { issue(kt + 1, buf ^ 1); cp_wait1(); }
        else             { cp_wait0(); }
        __syncthreads();

        const uint32_t* Au = (const uint32_t*)Asm[buf];
        const uint32_t* Bu = (const uint32_t*)Bsm[buf];
#pragma unroll
        for (int ks = 0; ks < 4; ks++) {
            uint32_t a[4][4], b[4][2];
            const int c = ks * 8 + (lane & 3);
#pragma unroll
            for (int mt = 0; mt < 4; mt++) {
                int r = wm + mt * 16 + (lane >> 2);
                a[mt][0] = Au[r * GPAD + c]           + 0x1000u;
                a[mt][1] = Au[(r + 8) * GPAD + c]     + 0x1000u;
                a[mt][2] = Au[r * GPAD + c + 4]       + 0x1000u;
                a[mt][3] = Au[(r + 8) * GPAD + c + 4] + 0x1000u;
            }
#pragma unroll
            for (int nt = 0; nt < 4; nt++) {
                int n = wn + nt * 8 + (lane >> 2);
                b[nt][0] = Bu[n * GPAD + c]     + 0x1000u;
                b[nt][1] = Bu[n * GPAD + c + 4] + 0x1000u;
            }
#pragma unroll
            for (int mt = 0; mt < 4; mt++)
#pragma unroll
                for (int nt = 0; nt < 4; nt++)
                    mma_tf32(acc[mt][nt], a[mt], b[nt]);
        }
        __syncthreads();
    }

#pragma unroll
    for (int mt = 0; mt < 4; mt++) {
        int row = m0 + wm + mt * 16 + (lane >> 2);
#pragma unroll
        for (int nt = 0; nt < 4; nt++) {
            int col = n0 + wn + nt * 8 + (lane & 3) * 2;
            float b0 = bias[col], b1 = bias[col + 1];
            float2 v;
            v.x = acc[mt][nt][0] + b0; v.y = acc[mt][nt][1] + b1;
            *(float2*)&C[(size_t)row * N + col] = v;
            v.x = acc[mt][nt][2] + b0; v.y = acc[mt][nt][3] + b1;
            *(float2*)&C[(size_t)(row + 8) * N + col] = v;
        }
    }
}

/* ============ prep: RoPE(q)*scale, RoPE(k), v -> head-major tf32 ========= */
__global__ __launch_bounds__(256)
void prep_kernel(const float* __restrict__ qkv, const float* __restrict__ cosb,
                 const float* __restrict__ sinb)
{
    int idx = blockIdx.x * blockDim.x + threadIdx.x;
    if (idx >= SEQ * NH * HD) return;
    int d = idx % HD;
    int h = (idx / HD) % NH;
    int s = idx / (NH * HD);

    float c  = cosb[s * HD + d];
    float sn = sinb[s * HD + d];
    const float* row = qkv + (size_t)s * HID3 + h * HD;
    size_t dst = ((size_t)h * SEQ + s) * HD + d;

    {
        float x = row[d];
        float p = (d < 40) ? row[d + 40] : row[d - 40];
        float v = (d < 40) ? (x * c - p * sn) : (x * c + p * sn);
        g_q[dst] = __float_as_uint(v * ATT_SCALE) + 0x1000u;
    }
    {
        const float* rk = row + HID;
        float x = rk[d];
        float p = (d < 40) ? rk[d + 40] : rk[d - 40];
        float v = (d < 40) ? (x * c - p * sn) : (x * c + p * sn);
        g_k[dst] = __float_as_uint(v) + 0x1000u;
    }
    g_v[dst] = __float_as_uint(row[2 * HID + d]) + 0x1000u;
}

/* ===================== flash attention v2 (block-diag) =================== */
#define A2M 128
#define A2N 64
#define KVP 84
#define PPAD 68
#define SM_K(b)  (sm_u + (b) * (A2N * KVP))
#define SM_V(b)  (sm_u + (2 + (b)) * (A2N * KVP))
#define SM_P     (sm_u + 4 * (A2N * KVP))
#define ATT_SMEM ((4 * A2N * KVP + A2M * PPAD) * 4)

__global__ __launch_bounds__(256, 1)
void attn2_kernel(const uint32_t* __restrict__ gq, const uint32_t* __restrict__ gk,
                  const uint32_t* __restrict__ gv, float* __restrict__ outp)
{
    extern __shared__ uint32_t sm_u[];

    const int tid  = threadIdx.x;
    const int lane = tid & 31;
    const int warp = tid >> 5;
    const int qt   = blockIdx.x;
    const int img  = blockIdx.y;
    const int head = blockIdx.z;
    const int sq0  = img * IMG_BLK + qt * A2M;
    const int wq   = warp * 16;
    const int pr   = wq + (lane >> 2);

    {
        const uint32_t* src = gq + ((size_t)head * SEQ + sq0) * HD;
        for (int i = tid; i < A2M * (HD / 4); i += 256) {
            int r = i / (HD / 4), c4 = (i - r * (HD / 4)) * 4;
            *(uint4*)&sm_u[r * KVP + c4] = *(const uint4*)&src[r * HD + c4];
        }
    }
    __syncthreads();

    uint32_t aq[10][4];
#pragma unroll
    for (int ks = 0; ks < 10; ks++) {
        const int c = ks * 8 + (lane & 3);
        aq[ks][0] = sm_u[pr * KVP + c];
        aq[ks][1] = sm_u[(pr + 8) * KVP + c];
        aq[ks][2] = sm_u[pr * KVP + c + 4];
        aq[ks][3] = sm_u[(pr + 8) * KVP + c + 4];
    }
    __syncthreads();

    const uint32_t* kbase = gk + ((size_t)head * SEQ + img * IMG_BLK) * HD;
    const uint32_t* vbase = gv + ((size_t)head * SEQ + img * IMG_BLK) * HD;

    auto issue = [&](int jt, int b) {
        const uint32_t* ks_ = kbase + (size_t)jt * A2N * HD;
        const uint32_t* vs_ = vbase + (size_t)jt * A2N * HD;
        uint32_t* kd = SM_K(b);
        uint32_t* vd = SM_V(b);
        for (int i = tid; i < A2N * (HD / 4); i += 256) {
            int r = i / (HD / 4), c4 = (i - r * (HD / 4)) * 4;
            cp_async16(&kd[r * KVP + c4], &ks_[r * HD + c4]);
            cp_async16(&vd[r * KVP + c4], &vs_[r * HD + c4]);
        }
        cp_commit();
    };

    issue(0, 0);

    float o[10][4];
#pragma unroll
    for (int nt = 0; nt < 10; nt++)
#pragma unroll
        for (int r = 0; r < 4; r++) o[nt][r] = 0.f;
    float m0r = -1e30f, m1r = -1e30f, l0 = 0.f, l1 = 0.f;

    const int NT = IMG_BLK / A2N;
#pragma unroll 1
    for (int jt = 0; jt < NT; jt++) {
        const int buf = jt & 1;
        cp_wait0();
        __syncthreads();
        if (jt + 1 < NT) issue(jt + 1, buf ^ 1);

        const uint32_t* Kb = SM_K(buf);
        const uint32_t* Vb = SM_V(buf);

        float sacc[8][4];
#pragma unroll
        for (int nt = 0; nt < 8; nt++)
#pragma unroll
            for (int r = 0; r < 4; r++) sacc[nt][r] = 0.f;

#pragma unroll
        for (int ks = 0; ks < 10; ks++) {
            const int c = ks * 8 + (lane & 3);
#pragma unroll
            for (int nt = 0; nt < 8; nt++) {
                int n = nt * 8 + (lane >> 2);
                uint32_t bk[2];
                bk[0] = Kb[n * KVP + c];
                bk[1] = Kb[n * KVP + c + 4];
                mma_tf32(sacc[nt], aq[ks], bk);
            }
        }

        float mx0 = -1e30f, mx1 = -1e30f;
#pragma unroll
        for (int nt = 0; nt < 8; nt++) {
            mx0 = fmaxf(mx0, fmaxf(sacc[nt][0], sacc[nt][1]));
            mx1 = fmaxf(mx1, fmaxf(sacc[nt][2], sacc[nt][3]));
        }
        mx0 = fmaxf(mx0, __shfl_xor_sync(0xffffffffu, mx0, 1));
        mx0 = fmaxf(mx0, __shfl_xor_sync(0xffffffffu, mx0, 2));
        mx1 = fmaxf(mx1, __shfl_xor_sync(0xffffffffu, mx1, 1));
        mx1 = fmaxf(mx1, __shfl_xor_sync(0xffffffffu, mx1, 2));

        float mn0 = fmaxf(m0r, mx0), mn1 = fmaxf(m1r, mx1);
        float cor0 = __expf(m0r - mn0), cor1 = __expf(m1r - mn1);
        m0r = mn0; m1r = mn1;

        uint32_t* Ps = SM_P;
        float rs0 = 0.f, rs1 = 0.f;
#pragma unroll
        for (int nt = 0; nt < 8; nt++) {
            float p0 = __expf(sacc[nt][0] - mn0);
            float p1 = __expf(sacc[nt][1] - mn0);
            float p2 = __expf(sacc[nt][2] - mn1);
            float p3 = __expf(sacc[nt][3] - mn1);
            rs0 += p0 + p1;  rs1 += p2 + p3;
            int col = nt * 8 + (lane & 3) * 2;
            uint2 u01 = { __float_as_uint(p0) + 0x1000u, __float_as_uint(p1) + 0x1000u };
            *(uint2*)&Ps[pr * PPAD + col] = u01;
            uint2 u23 = { __float_as_uint(p2) + 0x1000u, __float_as_uint(p3) + 0x1000u };
            *(uint2*)&Ps[(pr + 8) * PPAD + col] = u23;
        }
        rs0 += __shfl_xor_sync(0xffffffffu, rs0, 1);
        rs0 += __shfl_xor_sync(0xffffffffu, rs0, 2);
        rs1 += __shfl_xor_sync(0xffffffffu, rs1, 1);
        rs1 += __shfl_xor_sync(0xffffffffu, rs1, 2);
        l0 = l0 * cor0 + rs0;
        l1 = l1 * cor1 + rs1;
#pragma unroll
        for (int nt = 0; nt < 10; nt++) {
            o[nt][0] *= cor0; o[nt][1] *= cor0;
            o[nt][2] *= cor1; o[nt][3] *= cor1;
        }

        __syncwarp();

#pragma unroll
        for (int ks = 0; ks < 8; ks++) {
            const int c = ks * 8 + (lane & 3);
            uint32_t ap[4];
            ap[0] = Ps[pr * PPAD + c];
            ap[1] = Ps[(pr + 8) * PPAD + c];
            ap[2] = Ps[pr * PPAD + c + 4];
            ap[3] = Ps[(pr + 8) * PPAD + c + 4];
#pragma unroll
            for (int nt = 0; nt < 10; nt++) {
                int n = nt * 8 + (lane >> 2);
                uint32_t bv[2];
                bv[0] = Vb[c * KVP + n];
                bv[1] = Vb[(c + 4) * KVP + n];
                mma_tf32(o[nt], ap, bv);
            }
        }
        __syncwarp();
    }

    float inv0 = 1.0f / l0, inv1 = 1.0f / l1;
    int srow = sq0 + pr;
#pragma unroll
    for (int nt = 0; nt < 10; nt++) {
        int col = head * HD + nt * 8 + (lane & 3) * 2;
        float2 v0 = { o[nt][0] * inv0, o[nt][1] * inv0 };
        *(float2*)&outp[(size_t)srow * HID + col] = v0;
        float2 v1 = { o[nt][2] * inv1, o[nt][3] * inv1 };
        *(float2*)&outp[(size_t)(srow + 8) * HID + col] = v1;
    }
}

/* ============================== launch =================================== */
extern "C" void kernel_launch(void* const* d_in, const int* in_sizes, int n_in,
                              void* d_out, int out_size)
{
    (void)in_sizes; (void)n_in; (void)out_size;
    const float* hidden = (const float*)d_in[0];
    const float* cosb   = (const float*)d_in[2];
    const float* sinb   = (const float*)d_in[3];
    const float* qkv_w  = (const float*)d_in[4];
    const float* qkv_b  = (const float*)d_in[5];
    const float* proj_w = (const float*)d_in[6];
    const float* proj_b = (const float*)d_in[7];
    float* out = (float*)d_out;

    float *qkv_ptr, *att_ptr;
    uint32_t *qp, *kp, *vp;
    cudaGetSymbolAddress((void**)&qkv_ptr, g_qkv);
    cudaGetSymbolAddress((void**)&att_ptr, g_att);
    cudaGetSymbolAddress((void**)&qp, g_q);
    cudaGetSymbolAddress((void**)&kp, g_k);
    cudaGetSymbolAddress((void**)&vp, g_v);

    cudaFuncSetAttribute(gemm_bias_kernel, cudaFuncAttributeMaxDynamicSharedMemorySize,
                         GEMM_SMEM);
    cudaFuncSetAttribute(attn2_kernel, cudaFuncAttributeMaxDynamicSharedMemorySize,
                         ATT_SMEM);

    dim3 g1(HID3 / GBN, SEQ / GBM);
    gemm_bias_kernel<<<g1, 256, GEMM_SMEM>>>(hidden, qkv_w, qkv_b, qkv_ptr,
                                             SEQ, HID3, HID);

    int total = SEQ * NH * HD;
    prep_kernel<<<(total + 255) / 256, 256>>>(qkv_ptr, cosb, sinb);

    dim3 ga(IMG_BLK / A2M, 4, NH);
    attn2_kernel<<<ga, 256, ATT_SMEM>>>(qp, kp, vp, att_ptr);

    dim3 g3(HID / GBN, SEQ / GBM);
    gemm_bias_kernel<<<g3, 256, GEMM_SMEM>>>(att_ptr, proj_w, proj_b, out,
                                             SEQ, HID, HID);
}

// round 5
// speedup vs baseline: 1.1444x; 1.1444x over previous
#include <cuda_runtime.h>
#include <cstdint>

#define SEQ   4096
#define HID   1280
#define NH    16
#define HD    80
#define HID3  3840
#define IMG_BLK 1024
#define ATT_SCALE 0.11180339887498949f  /* 80^-0.5 */

/* ------------ scratch (device globals: allocation-free rule) ------------- */
__device__ float    g_qkv[(size_t)SEQ * HID3];
__device__ float    g_att[(size_t)SEQ * HID];
__device__ uint32_t g_q[(size_t)NH * SEQ * HD];
__device__ uint32_t g_k[(size_t)NH * SEQ * HD];
__device__ uint32_t g_v[(size_t)NH * SEQ * HD];

/* ----------------------------- helpers ---------------------------------- */
__device__ __forceinline__ void cp_async16(void* smem, const void* gmem) {
    uint32_t s = (uint32_t)__cvta_generic_to_shared(smem);
    asm volatile("cp.async.ca.shared.global [%0], [%1], 16;\n" :: "r"(s), "l"(gmem));
}
__device__ __forceinline__ void cp_commit() {
    asm volatile("cp.async.commit_group;\n" ::: "memory");
}
__device__ __forceinline__ void cp_wait0() {
    asm volatile("cp.async.wait_group 0;\n" ::: "memory");
}
__device__ __forceinline__ void cp_wait1() {
    asm volatile("cp.async.wait_group 1;\n" ::: "memory");
}

/* m16n8k8 tf32 mma, D += A*B (fp32 accum). Operands pre-rounded +0x1000. */
__device__ __forceinline__ void mma_tf32(float* d, const uint32_t* a, const uint32_t* b) {
    asm volatile(
        "mma.sync.aligned.m16n8k8.row.col.f32.tf32.tf32.f32 "
        "{%0,%1,%2,%3}, {%4,%5,%6,%7}, {%8,%9}, {%0,%1,%2,%3};\n"
        : "+f"(d[0]), "+f"(d[1]), "+f"(d[2]), "+f"(d[3])
        : "r"(a[0]), "r"(a[1]), "r"(a[2]), "r"(a[3]),
          "r"(b[0]), "r"(b[1]));
}

/* ldmatrix x4: four 8x8 b16 tiles (= 8 rows x 16B each) */
__device__ __forceinline__ void ldsm_x4(uint32_t* r, uint32_t saddr) {
    asm volatile(
        "ldmatrix.sync.aligned.m8n8.x4.shared.b16 {%0,%1,%2,%3}, [%4];\n"
        : "=r"(r[0]), "=r"(r[1]), "=r"(r[2]), "=r"(r[3]) : "r"(saddr));
}

/* ======================== GEMM: C = A * B^T + bias =======================
   A [M,K] fp32 row-major, B [N,K] fp32 row-major (weights), C [M,N].
   Block tile 128x128, BK=16, 8 warps (warp tile 64x32), tf32 mma via
   ldmatrix fragment loads, cp.async double-buffered smem. */
#define GBM 128
#define GBN 128
#define GBK 16
#define GPAD 20   /* stride 80B: LDSM 8-row phase hits distinct 16B groups */

__global__ __launch_bounds__(256, 2)
void gemm_bias_kernel(const float* __restrict__ A, const float* __restrict__ B,
                      const float* __restrict__ bias, float* __restrict__ C,
                      int M, int N, int K)
{
    __shared__ float As[2][GBM * GPAD];
    __shared__ float Bs[2][GBN * GPAD];

    const int tid  = threadIdx.x;
    const int lane = tid & 31;
    const int warp = tid >> 5;
    const int wm   = (warp & 1) * 64;
    const int wn   = (warp >> 1) * 32;
    const int m0   = blockIdx.y * GBM;
    const int n0   = blockIdx.x * GBN;
    const int KT   = K / GBK;

    /* ldmatrix per-lane row/col mapping
       A (x4 = frag a0..a3): t0-7 rows+0 k0, t8-15 rows+8 k0,
                             t16-23 rows+0 k4, t24-31 rows+8 k4   */
    const int a_row = wm + ((lane >> 3) & 1) * 8 + (lane & 7);
    const int a_col = (lane >> 4) * 4;
    /* B (x4 = b[2p],b[2p+1]): t0-7 n+0 k0, t8-15 n+0 k4,
                               t16-23 n+8 k0, t24-31 n+8 k4       */
    const int b_row = wn + ((lane >> 4) & 1) * 8 + (lane & 7);
    const int b_col = ((lane >> 3) & 1) * 4;

    const uint32_t As0 = (uint32_t)__cvta_generic_to_shared(&As[0][0]);
    const uint32_t Bs0 = (uint32_t)__cvta_generic_to_shared(&Bs[0][0]);

    float acc[4][4][4];
#pragma unroll
    for (int mt = 0; mt < 4; mt++)
#pragma unroll
        for (int nt = 0; nt < 4; nt++)
#pragma unroll
            for (int r = 0; r < 4; r++) acc[mt][nt][r] = 0.f;

    auto issue = [&](int kt, int buf) {
        int k0 = kt * GBK;
#pragma unroll
        for (int i = 0; i < 2; i++) {
            int f   = tid + i * 256;
            int row = f >> 2;
            int fc  = (f & 3) * 4;
            cp_async16(&As[buf][row * GPAD + fc], &A[(size_t)(m0 + row) * K + k0 + fc]);
            cp_async16(&Bs[buf][row * GPAD + fc], &B[(size_t)(n0 + row) * K + k0 + fc]);
        }
        cp_commit();
    };

    issue(0, 0);

#pragma unroll 1
    for (int kt = 0; kt < KT; kt++) {
        int buf = kt & 1;
        if (kt + 1 < KT) { issue(kt + 1, buf ^ 1); cp_wait1(); }
        else             { cp_wait0(); }
        __syncthreads();

        const uint32_t Ab = As0 + (uint32_t)buf * (GBM * GPAD * 4);
        const uint32_t Bb = Bs0 + (uint32_t)buf * (GBN * GPAD * 4);

#pragma unroll
        for (int ks = 0; ks < 2; ks++) {
            uint32_t a[4][4], b[2][4];
#pragma unroll
            for (int mt = 0; mt < 4; mt++) {
                uint32_t ad = Ab + (((a_row + mt * 16) * GPAD + a_col + ks * 8) << 2);
                ldsm_x4(a[mt], ad);
                a[mt][0] += 0x1000u; a[mt][1] += 0x1000u;
                a[mt][2] += 0x1000u; a[mt][3] += 0x1000u;
            }
#pragma unroll
            for (int p = 0; p < 2; p++) {
                uint32_t bd = Bb + (((b_row + p * 16) * GPAD + b_col + ks * 8) << 2);
                ldsm_x4(b[p], bd);
                b[p][0] += 0x1000u; b[p][1] += 0x1000u;
                b[p][2] += 0x1000u; b[p][3] += 0x1000u;
            }
#pragma unroll
            for (int mt = 0; mt < 4; mt++)
#pragma unroll
                for (int nt = 0; nt < 4; nt++)
                    mma_tf32(acc[mt][nt], a[mt], &b[nt >> 1][(nt & 1) * 2]);
        }
        __syncthreads();
    }

#pragma unroll
    for (int mt = 0; mt < 4; mt++) {
        int row = m0 + wm + mt * 16 + (lane >> 2);
#pragma unroll
        for (int nt = 0; nt < 4; nt++) {
            int col = n0 + wn + nt * 8 + (lane & 3) * 2;
            float b0 = bias[col], b1 = bias[col + 1];
            float2 v;
            v.x = acc[mt][nt][0] + b0; v.y = acc[mt][nt][1] + b1;
            *(float2*)&C[(size_t)row * N + col] = v;
            v.x = acc[mt][nt][2] + b0; v.y = acc[mt][nt][3] + b1;
            *(float2*)&C[(size_t)(row + 8) * N + col] = v;
        }
    }
}

/* ============ prep: RoPE(q)*scale, RoPE(k), v -> head-major tf32 ========= */
__global__ __launch_bounds__(256)
void prep_kernel(const float* __restrict__ qkv, const float* __restrict__ cosb,
                 const float* __restrict__ sinb)
{
    int idx = blockIdx.x * blockDim.x + threadIdx.x;
    if (idx >= SEQ * NH * HD) return;
    int d = idx % HD;
    int h = (idx / HD) % NH;
    int s = idx / (NH * HD);

    float c  = cosb[s * HD + d];
    float sn = sinb[s * HD + d];
    const float* row = qkv + (size_t)s * HID3 + h * HD;
    size_t dst = ((size_t)h * SEQ + s) * HD + d;

    {
        float x = row[d];
        float p = (d < 40) ? row[d + 40] : row[d - 40];
        float v = (d < 40) ? (x * c - p * sn) : (x * c + p * sn);
        g_q[dst] = __float_as_uint(v * ATT_SCALE) + 0x1000u;
    }
    {
        const float* rk = row + HID;
        float x = rk[d];
        float p = (d < 40) ? rk[d + 40] : rk[d - 40];
        float v = (d < 40) ? (x * c - p * sn) : (x * c + p * sn);
        g_k[dst] = __float_as_uint(v) + 0x1000u;
    }
    g_v[dst] = __float_as_uint(row[2 * HID + d]) + 0x1000u;
}

/* ===================== flash attention v2 (block-diag) =================== */
#define A2M 128
#define A2N 64
#define KVP 84
#define PPAD 68
#define SM_K(b)  (sm_u + (b) * (A2N * KVP))
#define SM_V(b)  (sm_u + (2 + (b)) * (A2N * KVP))
#define SM_P     (sm_u + 4 * (A2N * KVP))
#define ATT_SMEM ((4 * A2N * KVP + A2M * PPAD) * 4)

__global__ __launch_bounds__(256, 1)
void attn2_kernel(const uint32_t* __restrict__ gq, const uint32_t* __restrict__ gk,
                  const uint32_t* __restrict__ gv, float* __restrict__ outp)
{
    extern __shared__ uint32_t sm_u[];

    const int tid  = threadIdx.x;
    const int lane = tid & 31;
    const int warp = tid >> 5;
    const int qt   = blockIdx.x;
    const int img  = blockIdx.y;
    const int head = blockIdx.z;
    const int sq0  = img * IMG_BLK + qt * A2M;
    const int wq   = warp * 16;
    const int pr   = wq + (lane >> 2);

    {
        const uint32_t* src = gq + ((size_t)head * SEQ + sq0) * HD;
        for (int i = tid; i < A2M * (HD / 4); i += 256) {
            int r = i / (HD / 4), c4 = (i - r * (HD / 4)) * 4;
            *(uint4*)&sm_u[r * KVP + c4] = *(const uint4*)&src[r * HD + c4];
        }
    }
    __syncthreads();

    uint32_t aq[10][4];
#pragma unroll
    for (int ks = 0; ks < 10; ks++) {
        const int c = ks * 8 + (lane & 3);
        aq[ks][0] = sm_u[pr * KVP + c];
        aq[ks][1] = sm_u[(pr + 8) * KVP + c];
        aq[ks][2] = sm_u[pr * KVP + c + 4];
        aq[ks][3] = sm_u[(pr + 8) * KVP + c + 4];
    }
    __syncthreads();

    const uint32_t* kbase = gk + ((size_t)head * SEQ + img * IMG_BLK) * HD;
    const uint32_t* vbase = gv + ((size_t)head * SEQ + img * IMG_BLK) * HD;

    auto issue = [&](int jt, int b) {
        const uint32_t* ks_ = kbase + (size_t)jt * A2N * HD;
        const uint32_t* vs_ = vbase + (size_t)jt * A2N * HD;
        uint32_t* kd = SM_K(b);
        uint32_t* vd = SM_V(b);
        for (int i = tid; i < A2N * (HD / 4); i += 256) {
            int r = i / (HD / 4), c4 = (i - r * (HD / 4)) * 4;
            cp_async16(&kd[r * KVP + c4], &ks_[r * HD + c4]);
            cp_async16(&vd[r * KVP + c4], &vs_[r * HD + c4]);
        }
        cp_commit();
    };

    issue(0, 0);

    float o[10][4];
#pragma unroll
    for (int nt = 0; nt < 10; nt++)
#pragma unroll
        for (int r = 0; r < 4; r++) o[nt][r] = 0.f;
    float m0r = -1e30f, m1r = -1e30f, l0 = 0.f, l1 = 0.f;

    const int NT = IMG_BLK / A2N;
#pragma unroll 1
    for (int jt = 0; jt < NT; jt++) {
        const int buf = jt & 1;
        cp_wait0();
        __syncthreads();
        if (jt + 1 < NT) issue(jt + 1, buf ^ 1);

        const uint32_t* Kb = SM_K(buf);
        const uint32_t* Vb = SM_V(buf);

        float sacc[8][4];
#pragma unroll
        for (int nt = 0; nt < 8; nt++)
#pragma unroll
            for (int r = 0; r < 4; r++) sacc[nt][r] = 0.f;

#pragma unroll
        for (int ks = 0; ks < 10; ks++) {
            const int c = ks * 8 + (lane & 3);
#pragma unroll
            for (int nt = 0; nt < 8; nt++) {
                int n = nt * 8 + (lane >> 2);
                uint32_t bk[2];
                bk[0] = Kb[n * KVP + c];
                bk[1] = Kb[n * KVP + c + 4];
                mma_tf32(sacc[nt], aq[ks], bk);
            }
        }

        float mx0 = -1e30f, mx1 = -1e30f;
#pragma unroll
        for (int nt = 0; nt < 8; nt++) {
            mx0 = fmaxf(mx0, fmaxf(sacc[nt][0], sacc[nt][1]));
            mx1 = fmaxf(mx1, fmaxf(sacc[nt][2], sacc[nt][3]));
        }
        mx0 = fmaxf(mx0, __shfl_xor_sync(0xffffffffu, mx0, 1));
        mx0 = fmaxf(mx0, __shfl_xor_sync(0xffffffffu, mx0, 2));
        mx1 = fmaxf(mx1, __shfl_xor_sync(0xffffffffu, mx1, 1));
        mx1 = fmaxf(mx1, __shfl_xor_sync(0xffffffffu, mx1, 2));

        float mn0 = fmaxf(m0r, mx0), mn1 = fmaxf(m1r, mx1);
        float cor0 = __expf(m0r - mn0), cor1 = __expf(m1r - mn1);
        m0r = mn0; m1r = mn1;

        uint32_t* Ps = SM_P;
        float rs0 = 0.f, rs1 = 0.f;
#pragma unroll
        for (int nt = 0; nt < 8; nt++) {
            float p0 = __expf(sacc[nt][0] - mn0);
            float p1 = __expf(sacc[nt][1] - mn0);
            float p2 = __expf(sacc[nt][2] - mn1);
            float p3 = __expf(sacc[nt][3] - mn1);
            rs0 += p0 + p1;  rs1 += p2 + p3;
            int col = nt * 8 + (lane & 3) * 2;
            uint2 u01 = { __float_as_uint(p0) + 0x1000u, __float_as_uint(p1) + 0x1000u };
            *(uint2*)&Ps[pr * PPAD + col] = u01;
            uint2 u23 = { __float_as_uint(p2) + 0x1000u, __float_as_uint(p3) + 0x1000u };
            *(uint2*)&Ps[(pr + 8) * PPAD + col] = u23;
        }
        rs0 += __shfl_xor_sync(0xffffffffu, rs0, 1);
        rs0 += __shfl_xor_sync(0xffffffffu, rs0, 2);
        rs1 += __shfl_xor_sync(0xffffffffu, rs1, 1);
        rs1 += __shfl_xor_sync(0xffffffffu, rs1, 2);
        l0 = l0 * cor0 + rs0;
        l1 = l1 * cor1 + rs1;
#pragma unroll
        for (int nt = 0; nt < 10; nt++) {
            o[nt][0] *= cor0; o[nt][1] *= cor0;
            o[nt][2] *= cor1; o[nt][3] *= cor1;
        }

        __syncwarp();

#pragma unroll
        for (int ks = 0; ks < 8; ks++) {
            const int c = ks * 8 + (lane & 3);
            uint32_t ap[4];
            ap[0] = Ps[pr * PPAD + c];
            ap[1] = Ps[(pr + 8) * PPAD + c];
            ap[2] = Ps[pr * PPAD + c + 4];
            ap[3] = Ps[(pr + 8) * PPAD + c + 4];
#pragma unroll
            for (int nt = 0; nt < 10; nt++) {
                int n = nt * 8 + (lane >> 2);
                uint32_t bv[2];
                bv[0] = Vb[c * KVP + n];
                bv[1] = Vb[(c + 4) * KVP + n];
                mma_tf32(o[nt], ap, bv);
            }
        }
        __syncwarp();
    }

    float inv0 = 1.0f / l0, inv1 = 1.0f / l1;
    int srow = sq0 + pr;
#pragma unroll
    for (int nt = 0; nt < 10; nt++) {
        int col = head * HD + nt * 8 + (lane & 3) * 2;
        float2 v0 = { o[nt][0] * inv0, o[nt][1] * inv0 };
        *(float2*)&outp[(size_t)srow * HID + col] = v0;
        float2 v1 = { o[nt][2] * inv1, o[nt][3] * inv1 };
        *(float2*)&outp[(size_t)(srow + 8) * HID + col] = v1;
    }
}

/* ============================== launch =================================== */
extern "C" void kernel_launch(void* const* d_in, const int* in_sizes, int n_in,
                              void* d_out, int out_size)
{
    (void)in_sizes; (void)n_in; (void)out_size;
    const float* hidden = (const float*)d_in[0];
    const float* cosb   = (const float*)d_in[2];
    const float* sinb   = (const float*)d_in[3];
    const float* qkv_w  = (const float*)d_in[4];
    const float* qkv_b  = (const float*)d_in[5];
    const float* proj_w = (const float*)d_in[6];
    const float* proj_b = (const float*)d_in[7];
    float* out = (float*)d_out;

    float *qkv_ptr, *att_ptr;
    uint32_t *qp, *kp, *vp;
    cudaGetSymbolAddress((void**)&qkv_ptr, g_qkv);
    cudaGetSymbolAddress((void**)&att_ptr, g_att);
    cudaGetSymbolAddress((void**)&qp, g_q);
    cudaGetSymbolAddress((void**)&kp, g_k);
    cudaGetSymbolAddress((void**)&vp, g_v);

    cudaFuncSetAttribute(attn2_kernel, cudaFuncAttributeMaxDynamicSharedMemorySize,
                         ATT_SMEM);

    dim3 g1(HID3 / GBN, SEQ / GBM);
    gemm_bias_kernel<<<g1, 256>>>(hidden, qkv_w, qkv_b, qkv_ptr, SEQ, HID3, HID);

    int total = SEQ * NH * HD;
    prep_kernel<<<(total + 255) / 256, 256>>>(qkv_ptr, cosb, sinb);

    dim3 ga(IMG_BLK / A2M, 4, NH);
    attn2_kernel<<<ga, 256, ATT_SMEM>>>(qp, kp, vp, att_ptr);

    dim3 g3(HID / GBN, SEQ / GBM);
    gemm_bias_kernel<<<g3, 256>>>(att_ptr, proj_w, proj_b, out, SEQ, HID, HID);
}